// round 2
// baseline (speedup 1.0000x reference)
#include <cuda_runtime.h>

#define NN   100000
#define NE   1600000
#define FIN  11
#define HDIM 128
#define DOUT 64
#define LN_EPS 1e-5f

// ---------------- scratch (static device globals; no allocation) -------------
__device__ int   g_deg[NN];
__device__ int   g_rowptr[NN + 1];
__device__ int   g_cursor[NN];
__device__ int   g_srcsorted[NE];
__device__ float g_bufA[(size_t)NN * HDIM];
__device__ float g_bufB[(size_t)NN * HDIM];

__device__ __forceinline__ float warpsum(float v) {
#pragma unroll
    for (int o = 16; o; o >>= 1) v += __shfl_xor_sync(0xffffffffu, v, o);
    return v;
}

// ---------------- CSR build --------------------------------------------------
__global__ void k_zero_deg() {
    int i = blockIdx.x * blockDim.x + threadIdx.x;
    if (i < NN) g_deg[i] = 0;
}

__global__ void k_count(const int* __restrict__ tgt) {
    int e = blockIdx.x * blockDim.x + threadIdx.x;
    if (e < NE) atomicAdd(&g_deg[tgt[e]], 1);
}

// single-block exclusive scan of g_deg -> g_rowptr / g_cursor
__global__ void k_scan() {
    __shared__ int part[1024];
    int t = threadIdx.x;
    const int C = (NN + 1023) / 1024;
    int start = t * C;
    int end   = min(start + C, NN);
    int s = 0;
    for (int i = start; i < end; i++) s += g_deg[i];
    part[t] = s;
    __syncthreads();
    for (int off = 1; off < 1024; off <<= 1) {
        int v = (t >= off) ? part[t - off] : 0;
        __syncthreads();
        part[t] += v;
        __syncthreads();
    }
    int run = (t == 0) ? 0 : part[t - 1];
    for (int i = start; i < end; i++) {
        g_rowptr[i] = run;
        g_cursor[i] = run;
        run += g_deg[i];
    }
    if (t == 1023) g_rowptr[NN] = part[1023];
}

__global__ void k_scatter(const int* __restrict__ src, const int* __restrict__ tgt) {
    int e = blockIdx.x * blockDim.x + threadIdx.x;
    if (e < NE) {
        int tg = tgt[e];
        int p = atomicAdd(&g_cursor[tg], 1);
        g_srcsorted[p] = src[e];
    }
}

// ---------------- aggregation kernels (warp per node, CSR gather) ------------
// mean-aggregate 11-dim raw features
__global__ void k_agg_small(const float* __restrict__ feat, float* __restrict__ out) {
    int n    = (blockIdx.x * blockDim.x + threadIdx.x) >> 5;
    int lane = threadIdx.x & 31;
    if (n >= NN) return;
    int beg = g_rowptr[n], end = g_rowptr[n + 1];
    float acc = 0.f;
    for (int base = beg; base < end; base += 32) {
        int idx = (base + lane < end) ? g_srcsorted[base + lane] : 0;
        int cnt = min(32, end - base);
        for (int j = 0; j < cnt; j++) {
            int s = __shfl_sync(0xffffffffu, idx, j);
            if (lane < FIN) acc += feat[(size_t)s * FIN + lane];
        }
    }
    float inv = 1.f / (float)max(end - beg, 1);
    if (lane < FIN) out[(size_t)n * FIN + lane] = acc * inv;
}

// mean-aggregate 128-dim rows (float4 per lane)
__global__ void k_agg128(const float* __restrict__ in, float* __restrict__ out) {
    int n    = (blockIdx.x * blockDim.x + threadIdx.x) >> 5;
    int lane = threadIdx.x & 31;
    if (n >= NN) return;
    int beg = g_rowptr[n], end = g_rowptr[n + 1];
    float4 acc = make_float4(0.f, 0.f, 0.f, 0.f);
    for (int base = beg; base < end; base += 32) {
        int idx = (base + lane < end) ? g_srcsorted[base + lane] : 0;
        int cnt = min(32, end - base);
        for (int j = 0; j < cnt; j++) {
            int s = __shfl_sync(0xffffffffu, idx, j);
            float4 v = *(const float4*)(in + (size_t)s * HDIM + lane * 4);
            acc.x += v.x; acc.y += v.y; acc.z += v.z; acc.w += v.w;
        }
    }
    float inv = 1.f / (float)max(end - beg, 1);
    float4* o = (float4*)(out + (size_t)n * HDIM);
    o[lane] = make_float4(acc.x * inv, acc.y * inv, acc.z * inv, acc.w * inv);
}

// mean-aggregate 64-dim rows + LayerNorm (final layer output)
__global__ void k_agg64_ln(const float* __restrict__ in,
                           const float* __restrict__ gam,
                           const float* __restrict__ bet,
                           float* __restrict__ out) {
    int n    = (blockIdx.x * blockDim.x + threadIdx.x) >> 5;
    int lane = threadIdx.x & 31;
    if (n >= NN) return;
    int beg = g_rowptr[n], end = g_rowptr[n + 1];
    float2 acc = make_float2(0.f, 0.f);
    for (int base = beg; base < end; base += 32) {
        int idx = (base + lane < end) ? g_srcsorted[base + lane] : 0;
        int cnt = min(32, end - base);
        for (int j = 0; j < cnt; j++) {
            int s = __shfl_sync(0xffffffffu, idx, j);
            float2 v = *(const float2*)(in + (size_t)s * DOUT + lane * 2);
            acc.x += v.x; acc.y += v.y;
        }
    }
    float inv = 1.f / (float)max(end - beg, 1);
    acc.x *= inv; acc.y *= inv;
    float mu = warpsum(acc.x + acc.y) * (1.f / (float)DOUT);
    float dx = acc.x - mu, dy = acc.y - mu;
    float var = warpsum(dx * dx + dy * dy) * (1.f / (float)DOUT);
    float rstd = rsqrtf(var + LN_EPS);
    int c = lane * 2;
    float2 r;
    r.x = dx * rstd * gam[c]     + bet[c];
    r.y = dy * rstd * gam[c + 1] + bet[c + 1];
    *(float2*)(out + (size_t)n * DOUT + c) = r;
}

// ---------------- fused GEMM (+bias, optional LN/ReLU, deg-0 bias mask) ------
// out[n][c] = LN/ReLU( sum_k Y[n][k]*W[c][k] + (deg>0 ? b[c] : 0) )
template <int K, int OUT, bool LN, bool RELU, bool DEGMASK>
__global__ void __launch_bounds__(256)
k_gemm(const float* __restrict__ Y, const float* __restrict__ W,
       const float* __restrict__ bias, const float* __restrict__ gam,
       const float* __restrict__ bet, float* __restrict__ out) {
    constexpr int TM = 64;
    constexpr int J  = OUT / 16;   // cols per thread
    constexpr int Q  = OUT / 32;   // cols per lane in epilogue
    __shared__ __align__(16) float As[16][TM + 4];    // [k][m]
    __shared__ float Bs[16][OUT];                     // [k][c]  (= W[c][k])
    __shared__ float Cs[TM][OUT + 4];

    int tid = threadIdx.x;
    int tx = tid & 15, ty = tid >> 4;
    int rowbase = blockIdx.x * TM;

    float acc[4][J];
#pragma unroll
    for (int i = 0; i < 4; i++)
#pragma unroll
        for (int j = 0; j < J; j++) acc[i][j] = 0.f;

    for (int k0 = 0; k0 < K; k0 += 16) {
        // load A tile (transposed to [k][m])
#pragma unroll
        for (int l = tid; l < TM * 16; l += 256) {
            int m = l >> 4, k = l & 15;
            int row = rowbase + m, kk = k0 + k;
            float v = 0.f;
            if (row < NN && kk < K) v = Y[(size_t)row * K + kk];
            As[k][m] = v;
        }
        // load B tile: Bs[k][c] = W[c][k0+k]
#pragma unroll
        for (int l = tid; l < 16 * OUT; l += 256) {
            int c = l >> 4, k = l & 15;
            int kk = k0 + k;
            Bs[k][c] = (kk < K) ? W[(size_t)c * K + kk] : 0.f;
        }
        __syncthreads();
#pragma unroll
        for (int k = 0; k < 16; k++) {
            float4 a4 = *(const float4*)&As[k][ty * 4];
            float b[J];
#pragma unroll
            for (int j = 0; j < J; j++) b[j] = Bs[k][tx + 16 * j];
#pragma unroll
            for (int j = 0; j < J; j++) {
                acc[0][j] += a4.x * b[j];
                acc[1][j] += a4.y * b[j];
                acc[2][j] += a4.z * b[j];
                acc[3][j] += a4.w * b[j];
            }
        }
        __syncthreads();
    }

#pragma unroll
    for (int i = 0; i < 4; i++)
#pragma unroll
        for (int j = 0; j < J; j++) Cs[ty * 4 + i][tx + 16 * j] = acc[i][j];
    __syncthreads();

    int warp = tid >> 5, lane = tid & 31;
    for (int r = warp; r < TM; r += 8) {
        int node = rowbase + r;
        if (node >= NN) continue;
        bool addb = true;
        if (DEGMASK) addb = (g_rowptr[node + 1] - g_rowptr[node]) > 0;
        float v[Q];
        float s = 0.f;
#pragma unroll
        for (int q = 0; q < Q; q++) {
            int c = lane + 32 * q;
            v[q] = Cs[r][c] + (addb ? bias[c] : 0.f);
            s += v[q];
        }
        if (LN) {
            float mu = warpsum(s) * (1.f / (float)OUT);
            float vs = 0.f;
#pragma unroll
            for (int q = 0; q < Q; q++) { float d = v[q] - mu; vs += d * d; }
            float rstd = rsqrtf(warpsum(vs) * (1.f / (float)OUT) + LN_EPS);
#pragma unroll
            for (int q = 0; q < Q; q++) {
                int c = lane + 32 * q;
                float y = (v[q] - mu) * rstd * gam[c] + bet[c];
                if (RELU) y = fmaxf(y, 0.f);
                out[(size_t)node * OUT + c] = y;
            }
        } else {
#pragma unroll
            for (int q = 0; q < Q; q++) {
                int c = lane + 32 * q;
                out[(size_t)node * OUT + c] = v[q];
            }
        }
    }
}

// ---------------- launch -----------------------------------------------------
extern "C" void kernel_launch(void* const* d_in, const int* in_sizes, int n_in,
                              void* d_out, int out_size) {
    const float* feat = (const float*)d_in[0];
    const int*   ei   = (const int*)d_in[1];
    const float* W0 = (const float*)d_in[2];
    const float* b0 = (const float*)d_in[3];
    const float* W1 = (const float*)d_in[4];
    const float* b1 = (const float*)d_in[5];
    const float* W2 = (const float*)d_in[6];
    const float* b2 = (const float*)d_in[7];
    const float* g0 = (const float*)d_in[8];
    const float* be0 = (const float*)d_in[9];
    const float* g1 = (const float*)d_in[10];
    const float* be1 = (const float*)d_in[11];
    const float* g2 = (const float*)d_in[12];
    const float* be2 = (const float*)d_in[13];
    float* out = (float*)d_out;

    const int* src = ei;
    const int* tgt = ei + NE;

    float* bufA = nullptr;
    float* bufB = nullptr;
    cudaGetSymbolAddress((void**)&bufA, g_bufA);
    cudaGetSymbolAddress((void**)&bufB, g_bufB);

    const int TPB = 256;
    // CSR build
    k_zero_deg<<<(NN + TPB - 1) / TPB, TPB>>>();
    k_count<<<(NE + TPB - 1) / TPB, TPB>>>(tgt);
    k_scan<<<1, 1024>>>();
    k_scatter<<<(NE + TPB - 1) / TPB, TPB>>>(src, tgt);

    int agg_blocks  = (NN + 7) / 8;           // 8 warps/block, warp per node
    int gemm_blocks = (NN + 63) / 64;

    // Layer 0: aggregate(11) -> GEMM(11->128) + LN + ReLU (bias masked on deg=0)
    k_agg_small<<<agg_blocks, TPB>>>(feat, bufA);
    k_gemm<FIN, HDIM, true, true, true><<<gemm_blocks, 256>>>(bufA, W0, b0, g0, be0, bufB);

    // Layer 1: aggregate(128) -> GEMM(128->128) + LN + ReLU (bias masked)
    k_agg128<<<agg_blocks, TPB>>>(bufB, bufA);
    k_gemm<HDIM, HDIM, true, true, true><<<gemm_blocks, 256>>>(bufA, W1, b1, g1, be1, bufB);

    // Layer 2: GEMM(128->64)+bias first (reference order), then aggregate(64)+LN
    k_gemm<HDIM, DOUT, false, false, false><<<gemm_blocks, 256>>>(bufB, W2, b2, nullptr, nullptr, bufA);
    k_agg64_ln<<<agg_blocks, TPB>>>(bufA, g2, be2, out);
}

// round 6
// speedup vs baseline: 1.1473x; 1.1473x over previous
#include <cuda_runtime.h>
#include <cuda_fp16.h>

#define NN   100000
#define NE   1600000
#define FIN  11
#define FPAD 16
#define HDIM 128
#define DOUT 64
#define LN_EPS 1e-5f

// ---------------- scratch (static device globals; no allocation) -------------
__device__ int    g_deg[NN];
__device__ int    g_rowptr[NN + 1];
__device__ int    g_cursor[NN];
__device__ int    g_srcsorted[NE];
__device__ float  g_bufA[(size_t)NN * HDIM];   // fp32 scratch (agg outputs / gemm A)
__device__ float  g_bufB[(size_t)NN * HDIM];   // fp32 scratch
__device__ __half g_h0[(size_t)NN * HDIM];     // gemm0 out (gathered by agg128)
__device__ __half g_h1[(size_t)NN * DOUT];     // gemm2 out (gathered by agg64)
__device__ __half g_fh[(size_t)NN * FPAD];     // padded fp16 features

__device__ __forceinline__ float warpsum(float v) {
#pragma unroll
    for (int o = 16; o; o >>= 1) v += __shfl_xor_sync(0xffffffffu, v, o);
    return v;
}

// ---------------- CSR build --------------------------------------------------
__global__ void k_zero_deg() {
    int i = blockIdx.x * blockDim.x + threadIdx.x;
    if (i < NN) g_deg[i] = 0;
}

__global__ void k_count(const int* __restrict__ tgt) {
    int e = blockIdx.x * blockDim.x + threadIdx.x;
    if (e < NE) atomicAdd(&g_deg[tgt[e]], 1);
}

__global__ void k_scan() {
    __shared__ int part[1024];
    int t = threadIdx.x;
    const int C = (NN + 1023) / 1024;
    int start = t * C;
    int end   = min(start + C, NN);
    int s = 0;
    for (int i = start; i < end; i++) s += g_deg[i];
    part[t] = s;
    __syncthreads();
    for (int off = 1; off < 1024; off <<= 1) {
        int v = (t >= off) ? part[t - off] : 0;
        __syncthreads();
        part[t] += v;
        __syncthreads();
    }
    int run = (t == 0) ? 0 : part[t - 1];
    for (int i = start; i < end; i++) {
        g_rowptr[i] = run;
        g_cursor[i] = run;
        run += g_deg[i];
    }
    if (t == 1023) g_rowptr[NN] = part[1023];
}

__global__ void k_scatter(const int* __restrict__ src, const int* __restrict__ tgt) {
    int e = blockIdx.x * blockDim.x + threadIdx.x;
    if (e < NE) {
        int tg = tgt[e];
        int p = atomicAdd(&g_cursor[tg], 1);
        g_srcsorted[p] = src[e];
    }
}

// ---------------- feature pad/convert: fp32[11] -> fp16[16] ------------------
__global__ void k_feat2h(const float* __restrict__ feat) {
    int i = blockIdx.x * blockDim.x + threadIdx.x;
    if (i >= NN * FPAD) return;
    int n = i >> 4, c = i & 15;
    g_fh[i] = (c < FIN) ? __float2half(feat[(size_t)n * FIN + c]) : __float2half(0.f);
}

// ---------------- aggregation kernels ----------------------------------------
// mean-aggregate padded 16-dim fp16 features -> fp32 [n][16]
// two edges per step: lanes 0-15 edge j, lanes 16-31 edge j+1
__global__ void k_agg_small(float* __restrict__ out) {
    int n    = (blockIdx.x * blockDim.x + threadIdx.x) >> 5;
    int lane = threadIdx.x & 31;
    if (n >= NN) return;
    int beg = g_rowptr[n], end = g_rowptr[n + 1];
    float acc = 0.f;
    for (int base = beg; base < end; base += 32) {
        int idx = (base + lane < end) ? g_srcsorted[base + lane] : 0;
        int cnt = min(32, end - base);
        for (int j = 0; j < cnt; j += 2) {
            int s0 = __shfl_sync(0xffffffffu, idx, j);
            int s1 = __shfl_sync(0xffffffffu, idx, (j + 1) & 31);
            int s  = (lane < 16) ? s0 : ((j + 1 < cnt) ? s1 : -1);
            if (s >= 0) acc += __half2float(g_fh[(size_t)s * FPAD + (lane & 15)]);
        }
    }
    acc += __shfl_down_sync(0xffffffffu, acc, 16);
    float inv = 1.f / (float)max(end - beg, 1);
    if (lane < 16) out[(size_t)n * FPAD + lane] = acc * inv;
}

// mean-aggregate 128-dim fp16 rows -> fp32 (4 halves per lane = 8B, 256B/warp)
__global__ void k_agg128h(float* __restrict__ out) {
    int n    = (blockIdx.x * blockDim.x + threadIdx.x) >> 5;
    int lane = threadIdx.x & 31;
    if (n >= NN) return;
    int beg = g_rowptr[n], end = g_rowptr[n + 1];
    float4 acc = make_float4(0.f, 0.f, 0.f, 0.f);
    for (int base = beg; base < end; base += 32) {
        int idx = (base + lane < end) ? g_srcsorted[base + lane] : 0;
        int cnt = min(32, end - base);
#pragma unroll 4
        for (int j = 0; j < cnt; j++) {
            int s = __shfl_sync(0xffffffffu, idx, j);
            uint2 raw = *(const uint2*)(g_h0 + (size_t)s * HDIM + lane * 4);
            float2 f0 = __half22float2(*(__half2*)&raw.x);
            float2 f1 = __half22float2(*(__half2*)&raw.y);
            acc.x += f0.x; acc.y += f0.y; acc.z += f1.x; acc.w += f1.y;
        }
    }
    float inv = 1.f / (float)max(end - beg, 1);
    float4* o = (float4*)(out + (size_t)n * HDIM + lane * 4);
    *o = make_float4(acc.x * inv, acc.y * inv, acc.z * inv, acc.w * inv);
}

// mean-aggregate 64-dim fp16 rows + LayerNorm -> final fp32 output
__global__ void k_agg64_ln(const float* __restrict__ gam,
                           const float* __restrict__ bet,
                           float* __restrict__ out) {
    int n    = (blockIdx.x * blockDim.x + threadIdx.x) >> 5;
    int lane = threadIdx.x & 31;
    if (n >= NN) return;
    int beg = g_rowptr[n], end = g_rowptr[n + 1];
    float2 acc = make_float2(0.f, 0.f);
    for (int base = beg; base < end; base += 32) {
        int idx = (base + lane < end) ? g_srcsorted[base + lane] : 0;
        int cnt = min(32, end - base);
#pragma unroll 4
        for (int j = 0; j < cnt; j++) {
            int s = __shfl_sync(0xffffffffu, idx, j);
            float2 f = __half22float2(*(const __half2*)(g_h1 + (size_t)s * DOUT + lane * 2));
            acc.x += f.x; acc.y += f.y;
        }
    }
    float inv = 1.f / (float)max(end - beg, 1);
    acc.x *= inv; acc.y *= inv;
    float mu = warpsum(acc.x + acc.y) * (1.f / (float)DOUT);
    float dx = acc.x - mu, dy = acc.y - mu;
    float var = warpsum(dx * dx + dy * dy) * (1.f / (float)DOUT);
    float rstd = rsqrtf(var + LN_EPS);
    int c = lane * 2;
    float2 r;
    r.x = dx * rstd * gam[c]     + bet[c];
    r.y = dy * rstd * gam[c + 1] + bet[c + 1];
    *(float2*)(out + (size_t)n * DOUT + c) = r;
}

// ---------------- fused GEMM: TM=128, 8x(OUT/16) register tile ---------------
// out[n][c] = Epi( sum_k A[n][k]*W[c][k] + (deg>0||!DEGMASK ? b[c] : 0) )
// thread (tx,ty): rows ty*8..ty*8+7, cols {tx+16j}. Rows owned by one half-warp
// => LN stats via half-warp shuffles, no smem C staging.
template <int K, int KW, int OUT, bool LN, bool RELU, bool DEGMASK, bool OUTHALF>
__global__ void __launch_bounds__(256)
k_gemm(const float* __restrict__ A, const float* __restrict__ W,
       const float* __restrict__ bias, const float* __restrict__ gam,
       const float* __restrict__ bet,
       float* __restrict__ outF, __half* __restrict__ outH) {
    constexpr int TM = 128;
    constexpr int J  = OUT / 16;
    __shared__ __align__(16) float As[16][TM + 4];   // row stride 132 floats (16B-mult)
    __shared__ float Bs[16][OUT];

    int tid = threadIdx.x;
    int tx = tid & 15, ty = tid >> 4;
    int rowbase = blockIdx.x * TM;

    float acc[8][J];
#pragma unroll
    for (int i = 0; i < 8; i++)
#pragma unroll
        for (int j = 0; j < J; j++) acc[i][j] = 0.f;

    for (int k0 = 0; k0 < K; k0 += 16) {
        // A tile: float4 over k, transposed into As[k][m]
#pragma unroll
        for (int l = tid; l < TM * 4; l += 256) {
            int m = l >> 2, q = l & 3;
            int row = rowbase + m;
            float4 v = make_float4(0.f, 0.f, 0.f, 0.f);
            if (row < NN) v = *(const float4*)(A + (size_t)row * K + k0 + q * 4);
            As[q * 4 + 0][m] = v.x;
            As[q * 4 + 1][m] = v.y;
            As[q * 4 + 2][m] = v.z;
            As[q * 4 + 3][m] = v.w;
        }
        // B tile: Bs[k][c] = W[c][k0+k], zero-padded past KW
#pragma unroll
        for (int l = tid; l < 16 * OUT; l += 256) {
            int c = l >> 4, k = l & 15;
            int kk = k0 + k;
            Bs[k][c] = (kk < KW) ? W[(size_t)c * KW + kk] : 0.f;
        }
        __syncthreads();
#pragma unroll
        for (int k = 0; k < 16; k++) {
            float a[8];
            *(float4*)&a[0] = *(const float4*)&As[k][ty * 8];
            *(float4*)&a[4] = *(const float4*)&As[k][ty * 8 + 4];
            float b[J];
#pragma unroll
            for (int j = 0; j < J; j++) b[j] = Bs[k][tx + 16 * j];
#pragma unroll
            for (int i = 0; i < 8; i++)
#pragma unroll
                for (int j = 0; j < J; j++) acc[i][j] += a[i] * b[j];
        }
        __syncthreads();
    }

    // epilogue: LN stats via half-warp xor-shuffles (rows live in lanes 0-15/16-31)
#pragma unroll
    for (int i = 0; i < 8; i++) {
        int row = rowbase + ty * 8 + i;
        bool inb = row < NN;
        float bmul = 1.f;
        if (DEGMASK) {
            bool addb = inb && (g_rowptr[row + 1] - g_rowptr[row]) > 0;
            bmul = addb ? 1.f : 0.f;
        }
        float v[J];
        float s = 0.f;
#pragma unroll
        for (int j = 0; j < J; j++) {
            v[j] = acc[i][j] + bmul * bias[tx + 16 * j];
            s += v[j];
        }
        if (LN) {
#pragma unroll
            for (int o = 1; o < 16; o <<= 1) s += __shfl_xor_sync(0xffffffffu, s, o);
            float mu = s * (1.f / (float)OUT);
            float vs = 0.f;
#pragma unroll
            for (int j = 0; j < J; j++) { float d = v[j] - mu; vs += d * d; }
#pragma unroll
            for (int o = 1; o < 16; o <<= 1) vs += __shfl_xor_sync(0xffffffffu, vs, o);
            float rstd = rsqrtf(vs * (1.f / (float)OUT) + LN_EPS);
#pragma unroll
            for (int j = 0; j < J; j++) {
                int c = tx + 16 * j;
                float y = (v[j] - mu) * rstd * gam[c] + bet[c];
                if (RELU) y = fmaxf(y, 0.f);
                v[j] = y;
            }
        }
        if (inb) {
#pragma unroll
            for (int j = 0; j < J; j++) {
                int c = tx + 16 * j;
                if (OUTHALF) outH[(size_t)row * OUT + c] = __float2half(v[j]);
                else         outF[(size_t)row * OUT + c] = v[j];
            }
        }
    }
}

// ---------------- launch -----------------------------------------------------
extern "C" void kernel_launch(void* const* d_in, const int* in_sizes, int n_in,
                              void* d_out, int out_size) {
    const float* feat = (const float*)d_in[0];
    const int*   ei   = (const int*)d_in[1];
    const float* W0 = (const float*)d_in[2];
    const float* b0 = (const float*)d_in[3];
    const float* W1 = (const float*)d_in[4];
    const float* b1 = (const float*)d_in[5];
    const float* W2 = (const float*)d_in[6];
    const float* b2 = (const float*)d_in[7];
    const float* g0 = (const float*)d_in[8];
    const float* be0 = (const float*)d_in[9];
    const float* g1 = (const float*)d_in[10];
    const float* be1 = (const float*)d_in[11];
    const float* g2 = (const float*)d_in[12];
    const float* be2 = (const float*)d_in[13];
    float* out = (float*)d_out;

    const int* src = ei;
    const int* tgt = ei + NE;

    float* bufA = nullptr;
    float* bufB = nullptr;
    __half* h0 = nullptr;
    __half* h1 = nullptr;
    cudaGetSymbolAddress((void**)&bufA, g_bufA);
    cudaGetSymbolAddress((void**)&bufB, g_bufB);
    cudaGetSymbolAddress((void**)&h0, g_h0);
    cudaGetSymbolAddress((void**)&h1, g_h1);

    const int TPB = 256;
    // CSR build
    k_zero_deg<<<(NN + TPB - 1) / TPB, TPB>>>();
    k_count<<<(NE + TPB - 1) / TPB, TPB>>>(tgt);
    k_scan<<<1, 1024>>>();
    k_scatter<<<(NE + TPB - 1) / TPB, TPB>>>(src, tgt);

    // feature pad/convert
    k_feat2h<<<(NN * FPAD + TPB - 1) / TPB, TPB>>>(feat);

    int agg_blocks  = (NN + 7) / 8;             // warp per node, 8 warps/block
    int gemm_blocks = (NN + 127) / 128;

    // Layer 0: agg(16-dim fp16) -> GEMM(16->128)+LN+ReLU -> fp16
    k_agg_small<<<agg_blocks, TPB>>>(bufA);
    k_gemm<16, FIN, HDIM, true, true, true, true>
        <<<gemm_blocks, 256>>>(bufA, W0, b0, g0, be0, nullptr, h0);

    // Layer 1: agg(128 fp16) -> GEMM(128->128)+LN+ReLU -> fp32
    k_agg128h<<<agg_blocks, TPB>>>(bufA);
    k_gemm<HDIM, HDIM, HDIM, true, true, true, false>
        <<<gemm_blocks, 256>>>(bufA, W1, b1, g1, be1, bufB, nullptr);

    // Layer 2: GEMM(128->64)+bias -> fp16, then agg(64 fp16)+LN -> out
    k_gemm<HDIM, HDIM, DOUT, false, false, false, true>
        <<<gemm_blocks, 256>>>(bufB, W2, b2, nullptr, nullptr, nullptr, h1);
    k_agg64_ln<<<agg_blocks, TPB>>>(g2, be2, out);
}

// round 11
// speedup vs baseline: 1.3669x; 1.1914x over previous
#include <cuda_runtime.h>
#include <cuda_fp16.h>

#define NN   100000
#define NE   1600000
#define FIN  11
#define FPAD 16
#define HDIM 128
#define DOUT 64
#define LN_EPS 1e-5f
#define NB   ((NN + 1023) / 1024)   // 98 scan blocks

// ---------------- scratch (static device globals; no allocation) -------------
__device__ int    g_deg[NN];
__device__ int    g_rowptr[NN + 1];
__device__ int    g_cursor[NN];
__device__ int    g_srcsorted[NE];
__device__ int    g_bsum[128];
__device__ int    g_boff[128];
__device__ float  g_bufA[(size_t)NN * HDIM];
__device__ float  g_bufB[(size_t)NN * HDIM];
__device__ __half g_h0[(size_t)NN * HDIM];
__device__ __half g_h1[(size_t)NN * DOUT];
__device__ __half g_fh[(size_t)NN * FPAD];

__device__ __forceinline__ float warpsum(float v) {
#pragma unroll
    for (int o = 16; o; o >>= 1) v += __shfl_xor_sync(0xffffffffu, v, o);
    return v;
}
__device__ __forceinline__ int warpsum_i(int v) {
#pragma unroll
    for (int o = 16; o; o >>= 1) v += __shfl_xor_sync(0xffffffffu, v, o);
    return v;
}

// ---------------- CSR build --------------------------------------------------
__global__ void k_zero_deg() {
    int i = blockIdx.x * blockDim.x + threadIdx.x;
    if (i < NN) g_deg[i] = 0;
}

__global__ void k_count(const int* __restrict__ tgt) {
    int e = blockIdx.x * blockDim.x + threadIdx.x;
    if (e < NE) atomicAdd(&g_deg[tgt[e]], 1);
}

// scan stage 1: per-block (1024 elems) sums
__global__ void k_scan1() {
    __shared__ int ws[8];
    int b = blockIdx.x, t = threadIdx.x;
    int base = b * 1024 + t * 4;
    int s = 0;
#pragma unroll
    for (int i = 0; i < 4; i++) {
        int idx = base + i;
        if (idx < NN) s += g_deg[idx];
    }
    s = warpsum_i(s);
    if ((t & 31) == 0) ws[t >> 5] = s;
    __syncthreads();
    if (t < 8) {
        int v = ws[t];
#pragma unroll
        for (int o = 4; o; o >>= 1) v += __shfl_xor_sync(0xffu, v, o);
        if (t == 0) g_bsum[b] = v;
    }
}

// scan stage 2: exclusive scan of NB block sums (1 block, 128 threads)
__global__ void k_scan2() {
    __shared__ int wtot[4];
    int t = threadIdx.x;
    int v = (t < NB) ? g_bsum[t] : 0;
    int lane = t & 31, w = t >> 5;
    int incl = v;
#pragma unroll
    for (int o = 1; o < 32; o <<= 1) {
        int u = __shfl_up_sync(0xffffffffu, incl, o);
        if (lane >= o) incl += u;
    }
    if (lane == 31) wtot[w] = incl;
    __syncthreads();
    int woff = 0;
#pragma unroll
    for (int i = 0; i < 4; i++) woff += (i < w) ? wtot[i] : 0;
    if (t < NB) g_boff[t] = woff + incl - v;
}

// scan stage 3: block-local exclusive scan + offset -> rowptr/cursor
__global__ void k_scan3() {
    __shared__ int ws[8];
    int b = blockIdx.x, t = threadIdx.x;
    int base = b * 1024 + t * 4;
    int d[4];
    int s = 0;
#pragma unroll
    for (int i = 0; i < 4; i++) {
        int idx = base + i;
        d[i] = (idx < NN) ? g_deg[idx] : 0;
        s += d[i];
    }
    int lane = t & 31, w = t >> 5;
    int incl = s;
#pragma unroll
    for (int o = 1; o < 32; o <<= 1) {
        int u = __shfl_up_sync(0xffffffffu, incl, o);
        if (lane >= o) incl += u;
    }
    if (lane == 31) ws[w] = incl;
    __syncthreads();
    int woff = 0;
#pragma unroll
    for (int i = 0; i < 8; i++) woff += (i < w) ? ws[i] : 0;
    int run = g_boff[b] + woff + incl - s;
#pragma unroll
    for (int i = 0; i < 4; i++) {
        int idx = base + i;
        if (idx < NN) {
            g_rowptr[idx] = run;
            g_cursor[idx] = run;
            run += d[i];
        }
    }
    if (b == 0 && t == 0) g_rowptr[NN] = NE;
}

__global__ void k_scatter(const int* __restrict__ src, const int* __restrict__ tgt) {
    int e = blockIdx.x * blockDim.x + threadIdx.x;
    if (e < NE) {
        int tg = tgt[e];
        int p = atomicAdd(&g_cursor[tg], 1);
        g_srcsorted[p] = src[e];
    }
}

// ---------------- feature pad/convert: fp32[11] -> fp16[16] ------------------
__global__ void k_feat2h(const float* __restrict__ feat) {
    int i = blockIdx.x * blockDim.x + threadIdx.x;
    if (i >= NN * FPAD) return;
    int n = i >> 4, c = i & 15;
    g_fh[i] = (c < FIN) ? __float2half(feat[(size_t)n * FIN + c]) : __float2half(0.f);
}

// ---------------- aggregation kernels ----------------------------------------
__global__ void k_agg_small(float* __restrict__ out) {
    int n    = (blockIdx.x * blockDim.x + threadIdx.x) >> 5;
    int lane = threadIdx.x & 31;
    if (n >= NN) return;
    int beg = g_rowptr[n], end = g_rowptr[n + 1];
    float acc = 0.f;
    for (int base = beg; base < end; base += 32) {
        int idx = (base + lane < end) ? g_srcsorted[base + lane] : 0;
        int cnt = min(32, end - base);
        for (int j = 0; j < cnt; j += 2) {
            int s0 = __shfl_sync(0xffffffffu, idx, j);
            int s1 = __shfl_sync(0xffffffffu, idx, (j + 1) & 31);
            int s  = (lane < 16) ? s0 : ((j + 1 < cnt) ? s1 : -1);
            if (s >= 0) acc += __half2float(g_fh[(size_t)s * FPAD + (lane & 15)]);
        }
    }
    acc += __shfl_down_sync(0xffffffffu, acc, 16);
    float inv = 1.f / (float)max(end - beg, 1);
    if (lane < 16) out[(size_t)n * FPAD + lane] = acc * inv;
}

__global__ void k_agg128h(float* __restrict__ out) {
    int n    = (blockIdx.x * blockDim.x + threadIdx.x) >> 5;
    int lane = threadIdx.x & 31;
    if (n >= NN) return;
    int beg = g_rowptr[n], end = g_rowptr[n + 1];
    float4 acc = make_float4(0.f, 0.f, 0.f, 0.f);
    for (int base = beg; base < end; base += 32) {
        int idx = (base + lane < end) ? g_srcsorted[base + lane] : 0;
        int cnt = min(32, end - base);
#pragma unroll 4
        for (int j = 0; j < cnt; j++) {
            int s = __shfl_sync(0xffffffffu, idx, j);
            uint2 raw = *(const uint2*)(g_h0 + (size_t)s * HDIM + lane * 4);
            float2 f0 = __half22float2(*(__half2*)&raw.x);
            float2 f1 = __half22float2(*(__half2*)&raw.y);
            acc.x += f0.x; acc.y += f0.y; acc.z += f1.x; acc.w += f1.y;
        }
    }
    float inv = 1.f / (float)max(end - beg, 1);
    float4* o = (float4*)(out + (size_t)n * HDIM + lane * 4);
    *o = make_float4(acc.x * inv, acc.y * inv, acc.z * inv, acc.w * inv);
}

__global__ void k_agg64_ln(const float* __restrict__ gam,
                           const float* __restrict__ bet,
                           float* __restrict__ out) {
    int n    = (blockIdx.x * blockDim.x + threadIdx.x) >> 5;
    int lane = threadIdx.x & 31;
    if (n >= NN) return;
    int beg = g_rowptr[n], end = g_rowptr[n + 1];
    float2 acc = make_float2(0.f, 0.f);
    for (int base = beg; base < end; base += 32) {
        int idx = (base + lane < end) ? g_srcsorted[base + lane] : 0;
        int cnt = min(32, end - base);
#pragma unroll 4
        for (int j = 0; j < cnt; j++) {
            int s = __shfl_sync(0xffffffffu, idx, j);
            float2 f = __half22float2(*(const __half2*)(g_h1 + (size_t)s * DOUT + lane * 2));
            acc.x += f.x; acc.y += f.y;
        }
    }
    float inv = 1.f / (float)max(end - beg, 1);
    acc.x *= inv; acc.y *= inv;
    float mu = warpsum(acc.x + acc.y) * (1.f / (float)DOUT);
    float dx = acc.x - mu, dy = acc.y - mu;
    float var = warpsum(dx * dx + dy * dy) * (1.f / (float)DOUT);
    float rstd = rsqrtf(var + LN_EPS);
    int c = lane * 2;
    float2 r;
    r.x = dx * rstd * gam[c]     + bet[c];
    r.y = dy * rstd * gam[c + 1] + bet[c + 1];
    *(float2*)(out + (size_t)n * DOUT + c) = r;
}

// ---------------- fused GEMM with packed fma.rn.f32x2 ------------------------
// TM=128 rows/block, thread (tx,ty) owns rows ty*8..+7 (as 4 packed row-pairs)
// and cols {tx+16j}. As row pairs are adjacent -> LDS.64 gives packed a2.
// Bs2 stores (w,w) duplicated -> LDS.64 gives packed broadcast b2. No MOV packing.
template <int K, int KW, int OUT, bool LN, bool RELU, bool DEGMASK, bool OUTHALF>
__global__ void __launch_bounds__(256)
k_gemm(const float* __restrict__ A, const float* __restrict__ W,
       const float* __restrict__ bias, const float* __restrict__ gam,
       const float* __restrict__ bet,
       float* __restrict__ outF, __half* __restrict__ outH) {
    constexpr int TM = 128;
    constexpr int J  = OUT / 16;
    __shared__ __align__(16) float  As[16][TM + 4];   // 528B row stride (8B mult)
    __shared__ __align__(16) float2 Bs2[16][OUT];     // duplicated (w,w)

    int tid = threadIdx.x;
    int tx = tid & 15, ty = tid >> 4;
    int rowbase = blockIdx.x * TM;

    unsigned long long acc[4][J];   // f32x2 pairs: rows (2p, 2p+1)
#pragma unroll
    for (int p = 0; p < 4; p++)
#pragma unroll
        for (int j = 0; j < J; j++) acc[p][j] = 0ull;

    for (int k0 = 0; k0 < K; k0 += 16) {
        // A tile: float4 over k, transposed into As[k][m]
#pragma unroll
        for (int l = tid; l < TM * 4; l += 256) {
            int m = l >> 2, q = l & 3;
            int row = rowbase + m;
            float4 v = make_float4(0.f, 0.f, 0.f, 0.f);
            if (row < NN) v = *(const float4*)(A + (size_t)row * K + k0 + q * 4);
            As[q * 4 + 0][m] = v.x;
            As[q * 4 + 1][m] = v.y;
            As[q * 4 + 2][m] = v.z;
            As[q * 4 + 3][m] = v.w;
        }
        // B tile: Bs2[k][c] = (W[c][k0+k], W[c][k0+k])
#pragma unroll
        for (int l = tid; l < 16 * OUT; l += 256) {
            int c = l >> 4, k = l & 15;
            int kk = k0 + k;
            float w = (kk < KW) ? W[(size_t)c * KW + kk] : 0.f;
            Bs2[k][c] = make_float2(w, w);
        }
        __syncthreads();
#pragma unroll
        for (int k = 0; k < 16; k++) {
            unsigned long long a2[4];
#pragma unroll
            for (int p = 0; p < 4; p++)
                a2[p] = *(const unsigned long long*)&As[k][ty * 8 + 2 * p];
#pragma unroll
            for (int j = 0; j < J; j++) {
                unsigned long long b2 = *(const unsigned long long*)&Bs2[k][tx + 16 * j];
#pragma unroll
                for (int p = 0; p < 4; p++)
                    asm("fma.rn.f32x2 %0, %1, %2, %0;"
                        : "+l"(acc[p][j]) : "l"(a2[p]), "l"(b2));
            }
        }
        __syncthreads();
    }

    // epilogue: per-row LN via half-warp xor-shuffles
#pragma unroll
    for (int i = 0; i < 8; i++) {
        int row = rowbase + ty * 8 + i;
        bool inb = row < NN;
        float bmul = 1.f;
        if (DEGMASK) {
            bool addb = inb && (g_rowptr[row + 1] - g_rowptr[row]) > 0;
            bmul = addb ? 1.f : 0.f;
        }
        float v[J];
        float s = 0.f;
#pragma unroll
        for (int j = 0; j < J; j++) {
            float2 pr = *(const float2*)&acc[i >> 1][j];
            float a = (i & 1) ? pr.y : pr.x;
            v[j] = a + bmul * bias[tx + 16 * j];
            s += v[j];
        }
        if (LN) {
#pragma unroll
            for (int o = 1; o < 16; o <<= 1) s += __shfl_xor_sync(0xffffffffu, s, o);
            float mu = s * (1.f / (float)OUT);
            float vs = 0.f;
#pragma unroll
            for (int j = 0; j < J; j++) { float d = v[j] - mu; vs += d * d; }
#pragma unroll
            for (int o = 1; o < 16; o <<= 1) vs += __shfl_xor_sync(0xffffffffu, vs, o);
            float rstd = rsqrtf(vs * (1.f / (float)OUT) + LN_EPS);
#pragma unroll
            for (int j = 0; j < J; j++) {
                int c = tx + 16 * j;
                float y = (v[j] - mu) * rstd * gam[c] + bet[c];
                if (RELU) y = fmaxf(y, 0.f);
                v[j] = y;
            }
        }
        if (inb) {
#pragma unroll
            for (int j = 0; j < J; j++) {
                int c = tx + 16 * j;
                if (OUTHALF) outH[(size_t)row * OUT + c] = __float2half(v[j]);
                else         outF[(size_t)row * OUT + c] = v[j];
            }
        }
    }
}

// ---------------- launch -----------------------------------------------------
extern "C" void kernel_launch(void* const* d_in, const int* in_sizes, int n_in,
                              void* d_out, int out_size) {
    const float* feat = (const float*)d_in[0];
    const int*   ei   = (const int*)d_in[1];
    const float* W0 = (const float*)d_in[2];
    const float* b0 = (const float*)d_in[3];
    const float* W1 = (const float*)d_in[4];
    const float* b1 = (const float*)d_in[5];
    const float* W2 = (const float*)d_in[6];
    const float* b2 = (const float*)d_in[7];
    const float* g0 = (const float*)d_in[8];
    const float* be0 = (const float*)d_in[9];
    const float* g1 = (const float*)d_in[10];
    const float* be1 = (const float*)d_in[11];
    const float* g2 = (const float*)d_in[12];
    const float* be2 = (const float*)d_in[13];
    float* out = (float*)d_out;

    const int* src = ei;
    const int* tgt = ei + NE;

    float* bufA = nullptr;
    float* bufB = nullptr;
    __half* h0 = nullptr;
    __half* h1 = nullptr;
    cudaGetSymbolAddress((void**)&bufA, g_bufA);
    cudaGetSymbolAddress((void**)&bufB, g_bufB);
    cudaGetSymbolAddress((void**)&h0, g_h0);
    cudaGetSymbolAddress((void**)&h1, g_h1);

    const int TPB = 256;
    // CSR build
    k_zero_deg<<<(NN + TPB - 1) / TPB, TPB>>>();
    k_count<<<(NE + TPB - 1) / TPB, TPB>>>(tgt);
    k_scan1<<<NB, 256>>>();
    k_scan2<<<1, 128>>>();
    k_scan3<<<NB, 256>>>();
    k_scatter<<<(NE + TPB - 1) / TPB, TPB>>>(src, tgt);

    // feature pad/convert
    k_feat2h<<<(NN * FPAD + TPB - 1) / TPB, TPB>>>(feat);

    int agg_blocks  = (NN + 7) / 8;
    int gemm_blocks = (NN + 127) / 128;

    // Layer 0: agg(16 fp16) -> GEMM(16->128)+LN+ReLU -> fp16
    k_agg_small<<<agg_blocks, TPB>>>(bufA);
    k_gemm<16, FIN, HDIM, true, true, true, true>
        <<<gemm_blocks, 256>>>(bufA, W0, b0, g0, be0, nullptr, h0);

    // Layer 1: agg(128 fp16) -> GEMM(128->128)+LN+ReLU -> fp32
    k_agg128h<<<agg_blocks, TPB>>>(bufA);
    k_gemm<HDIM, HDIM, HDIM, true, true, true, false>
        <<<gemm_blocks, 256>>>(bufA, W1, b1, g1, be1, bufB, nullptr);

    // Layer 2: GEMM(128->64)+bias -> fp16, then agg(64 fp16)+LN -> out
    k_gemm<HDIM, HDIM, DOUT, false, false, false, true>
        <<<gemm_blocks, 256>>>(bufB, W2, b2, nullptr, nullptr, nullptr, h1);
    k_agg64_ln<<<agg_blocks, TPB>>>(g2, be2, out);
}

// round 15
// speedup vs baseline: 2.4814x; 1.8153x over previous
#include <cuda_runtime.h>
#include <cuda_fp16.h>
#include <cstdint>

#define NN   100000
#define NE   1600000
#define FIN  11
#define FPAD 16
#define HDIM 128
#define DOUT 64
#define LN_EPS 1e-5f
#define NB   ((NN + 1023) / 1024)

// ---------------- scratch (static device globals; no allocation) -------------
__device__ int    g_deg[NN];
__device__ int    g_rowptr[NN + 1];
__device__ int    g_cursor[NN];
__device__ int    g_srcsorted[NE];
__device__ int    g_bsum[128];
__device__ int    g_boff[128];
__device__ float  g_bufA[(size_t)NN * FPAD];   // agg_small out (fp32)
__device__ __half g_h0[(size_t)NN * HDIM];     // gemm0 out (gathered by agg128)
__device__ __half g_act1h[(size_t)NN * HDIM];  // agg128 out = gemm1 A (fp16)
__device__ __half g_y1h[(size_t)NN * HDIM];    // gemm1 out = gemm2 A (fp16)
__device__ __half g_h1[(size_t)NN * DOUT];     // gemm2 out (gathered by agg64)
__device__ __half g_fh[(size_t)NN * FPAD];     // padded fp16 features
__device__ __half g_w1h[HDIM * HDIM];          // W1 fp16
__device__ __half g_w2h[DOUT * HDIM];          // W2 fp16

__device__ __forceinline__ uint32_t smem_u32(const void* p) {
    uint32_t a;
    asm("{ .reg .u64 t; cvta.to.shared.u64 t, %1; cvt.u32.u64 %0, t; }"
        : "=r"(a) : "l"(p));
    return a;
}

__device__ __forceinline__ float warpsum(float v) {
#pragma unroll
    for (int o = 16; o; o >>= 1) v += __shfl_xor_sync(0xffffffffu, v, o);
    return v;
}
__device__ __forceinline__ int warpsum_i(int v) {
#pragma unroll
    for (int o = 16; o; o >>= 1) v += __shfl_xor_sync(0xffffffffu, v, o);
    return v;
}

// ---------------- CSR build --------------------------------------------------
__global__ void k_zero_deg() {
    int i = blockIdx.x * blockDim.x + threadIdx.x;
    if (i < NN) g_deg[i] = 0;
}

__global__ void k_count(const int* __restrict__ tgt) {
    int e = blockIdx.x * blockDim.x + threadIdx.x;
    if (e < NE) atomicAdd(&g_deg[tgt[e]], 1);
}

__global__ void k_scan1() {
    __shared__ int ws[8];
    int b = blockIdx.x, t = threadIdx.x;
    int base = b * 1024 + t * 4;
    int s = 0;
#pragma unroll
    for (int i = 0; i < 4; i++) {
        int idx = base + i;
        if (idx < NN) s += g_deg[idx];
    }
    s = warpsum_i(s);
    if ((t & 31) == 0) ws[t >> 5] = s;
    __syncthreads();
    if (t < 8) {
        int v = ws[t];
#pragma unroll
        for (int o = 4; o; o >>= 1) v += __shfl_xor_sync(0xffu, v, o);
        if (t == 0) g_bsum[b] = v;
    }
}

__global__ void k_scan2() {
    __shared__ int wtot[4];
    int t = threadIdx.x;
    int v = (t < NB) ? g_bsum[t] : 0;
    int lane = t & 31, w = t >> 5;
    int incl = v;
#pragma unroll
    for (int o = 1; o < 32; o <<= 1) {
        int u = __shfl_up_sync(0xffffffffu, incl, o);
        if (lane >= o) incl += u;
    }
    if (lane == 31) wtot[w] = incl;
    __syncthreads();
    int woff = 0;
#pragma unroll
    for (int i = 0; i < 4; i++) woff += (i < w) ? wtot[i] : 0;
    if (t < NB) g_boff[t] = woff + incl - v;
}

__global__ void k_scan3() {
    __shared__ int ws[8];
    int b = blockIdx.x, t = threadIdx.x;
    int base = b * 1024 + t * 4;
    int d[4];
    int s = 0;
#pragma unroll
    for (int i = 0; i < 4; i++) {
        int idx = base + i;
        d[i] = (idx < NN) ? g_deg[idx] : 0;
        s += d[i];
    }
    int lane = t & 31, w = t >> 5;
    int incl = s;
#pragma unroll
    for (int o = 1; o < 32; o <<= 1) {
        int u = __shfl_up_sync(0xffffffffu, incl, o);
        if (lane >= o) incl += u;
    }
    if (lane == 31) ws[w] = incl;
    __syncthreads();
    int woff = 0;
#pragma unroll
    for (int i = 0; i < 8; i++) woff += (i < w) ? ws[i] : 0;
    int run = g_boff[b] + woff + incl - s;
#pragma unroll
    for (int i = 0; i < 4; i++) {
        int idx = base + i;
        if (idx < NN) {
            g_rowptr[idx] = run;
            g_cursor[idx] = run;
            run += d[i];
        }
    }
    if (b == 0 && t == 0) g_rowptr[NN] = NE;
}

__global__ void k_scatter(const int* __restrict__ src, const int* __restrict__ tgt) {
    int e = blockIdx.x * blockDim.x + threadIdx.x;
    if (e < NE) {
        int tg = tgt[e];
        int p = atomicAdd(&g_cursor[tg], 1);
        g_srcsorted[p] = src[e];
    }
}

// ---------------- conversions ------------------------------------------------
__global__ void k_feat2h(const float* __restrict__ feat) {
    int i = blockIdx.x * blockDim.x + threadIdx.x;
    if (i >= NN * FPAD) return;
    int n = i >> 4, c = i & 15;
    g_fh[i] = (c < FIN) ? __float2half(feat[(size_t)n * FIN + c]) : __float2half(0.f);
}

__global__ void k_w2h(const float* __restrict__ W1, const float* __restrict__ W2) {
    int i = blockIdx.x * blockDim.x + threadIdx.x;
    if (i < HDIM * HDIM) g_w1h[i] = __float2half(W1[i]);
    else {
        int j = i - HDIM * HDIM;
        if (j < DOUT * HDIM) g_w2h[j] = __float2half(W2[j]);
    }
}

// ---------------- aggregation kernels ----------------------------------------
__global__ void k_agg_small(float* __restrict__ out) {
    int n    = (blockIdx.x * blockDim.x + threadIdx.x) >> 5;
    int lane = threadIdx.x & 31;
    if (n >= NN) return;
    int beg = g_rowptr[n], end = g_rowptr[n + 1];
    float acc = 0.f;
    for (int base = beg; base < end; base += 32) {
        int idx = (base + lane < end) ? g_srcsorted[base + lane] : 0;
        int cnt = min(32, end - base);
        for (int j = 0; j < cnt; j += 2) {
            int s0 = __shfl_sync(0xffffffffu, idx, j);
            int s1 = __shfl_sync(0xffffffffu, idx, (j + 1) & 31);
            int s  = (lane < 16) ? s0 : ((j + 1 < cnt) ? s1 : -1);
            if (s >= 0) acc += __half2float(g_fh[(size_t)s * FPAD + (lane & 15)]);
        }
    }
    acc += __shfl_down_sync(0xffffffffu, acc, 16);
    float inv = 1.f / (float)max(end - beg, 1);
    if (lane < 16) out[(size_t)n * FPAD + lane] = acc * inv;
}

// mean-aggregate 128-dim fp16 rows -> fp16 out (gemm1 A operand)
__global__ void k_agg128h() {
    int n    = (blockIdx.x * blockDim.x + threadIdx.x) >> 5;
    int lane = threadIdx.x & 31;
    if (n >= NN) return;
    int beg = g_rowptr[n], end = g_rowptr[n + 1];
    float4 acc = make_float4(0.f, 0.f, 0.f, 0.f);
    for (int base = beg; base < end; base += 32) {
        int idx = (base + lane < end) ? g_srcsorted[base + lane] : 0;
        int cnt = min(32, end - base);
#pragma unroll 4
        for (int j = 0; j < cnt; j++) {
            int s = __shfl_sync(0xffffffffu, idx, j);
            uint2 raw = *(const uint2*)(g_h0 + (size_t)s * HDIM + lane * 4);
            float2 f0 = __half22float2(*(__half2*)&raw.x);
            float2 f1 = __half22float2(*(__half2*)&raw.y);
            acc.x += f0.x; acc.y += f0.y; acc.z += f1.x; acc.w += f1.y;
        }
    }
    float inv = 1.f / (float)max(end - beg, 1);
    __half2 o0 = __floats2half2_rn(acc.x * inv, acc.y * inv);
    __half2 o1 = __floats2half2_rn(acc.z * inv, acc.w * inv);
    uint2 o;
    o.x = *(uint32_t*)&o0; o.y = *(uint32_t*)&o1;
    *(uint2*)(g_act1h + (size_t)n * HDIM + lane * 4) = o;
}

__global__ void k_agg64_ln(const float* __restrict__ gam,
                           const float* __restrict__ bet,
                           float* __restrict__ out) {
    int n    = (blockIdx.x * blockDim.x + threadIdx.x) >> 5;
    int lane = threadIdx.x & 31;
    if (n >= NN) return;
    int beg = g_rowptr[n], end = g_rowptr[n + 1];
    float2 acc = make_float2(0.f, 0.f);
    for (int base = beg; base < end; base += 32) {
        int idx = (base + lane < end) ? g_srcsorted[base + lane] : 0;
        int cnt = min(32, end - base);
#pragma unroll 4
        for (int j = 0; j < cnt; j++) {
            int s = __shfl_sync(0xffffffffu, idx, j);
            float2 f = __half22float2(*(const __half2*)(g_h1 + (size_t)s * DOUT + lane * 2));
            acc.x += f.x; acc.y += f.y;
        }
    }
    float inv = 1.f / (float)max(end - beg, 1);
    acc.x *= inv; acc.y *= inv;
    float mu = warpsum(acc.x + acc.y) * (1.f / (float)DOUT);
    float dx = acc.x - mu, dy = acc.y - mu;
    float var = warpsum(dx * dx + dy * dy) * (1.f / (float)DOUT);
    float rstd = rsqrtf(var + LN_EPS);
    int c = lane * 2;
    float2 r;
    r.x = dx * rstd * gam[c]     + bet[c];
    r.y = dy * rstd * gam[c + 1] + bet[c + 1];
    *(float2*)(out + (size_t)n * DOUT + c) = r;
}

// ---------------- layer-0 GEMM (FFMA2, K=16) ---------------------------------
template <int K, int KW, int OUT>
__global__ void __launch_bounds__(256)
k_gemm0(const float* __restrict__ A, const float* __restrict__ W,
        const float* __restrict__ bias, const float* __restrict__ gam,
        const float* __restrict__ bet, __half* __restrict__ outH) {
    constexpr int TM = 128;
    constexpr int J  = OUT / 16;
    __shared__ __align__(16) float  As[16][TM + 4];
    __shared__ __align__(16) float2 Bs2[16][OUT];

    int tid = threadIdx.x;
    int tx = tid & 15, ty = tid >> 4;
    int rowbase = blockIdx.x * TM;

    unsigned long long acc[4][J];
#pragma unroll
    for (int p = 0; p < 4; p++)
#pragma unroll
        for (int j = 0; j < J; j++) acc[p][j] = 0ull;

    for (int k0 = 0; k0 < K; k0 += 16) {
#pragma unroll
        for (int l = tid; l < TM * 4; l += 256) {
            int m = l >> 2, q = l & 3;
            int row = rowbase + m;
            float4 v = make_float4(0.f, 0.f, 0.f, 0.f);
            if (row < NN) v = *(const float4*)(A + (size_t)row * K + k0 + q * 4);
            As[q * 4 + 0][m] = v.x;
            As[q * 4 + 1][m] = v.y;
            As[q * 4 + 2][m] = v.z;
            As[q * 4 + 3][m] = v.w;
        }
#pragma unroll
        for (int l = tid; l < 16 * OUT; l += 256) {
            int c = l >> 4, k = l & 15;
            int kk = k0 + k;
            float w = (kk < KW) ? W[(size_t)c * KW + kk] : 0.f;
            Bs2[k][c] = make_float2(w, w);
        }
        __syncthreads();
#pragma unroll
        for (int k = 0; k < 16; k++) {
            unsigned long long a2[4];
#pragma unroll
            for (int p = 0; p < 4; p++)
                a2[p] = *(const unsigned long long*)&As[k][ty * 8 + 2 * p];
#pragma unroll
            for (int j = 0; j < J; j++) {
                unsigned long long b2 = *(const unsigned long long*)&Bs2[k][tx + 16 * j];
#pragma unroll
                for (int p = 0; p < 4; p++)
                    asm("fma.rn.f32x2 %0, %1, %2, %0;"
                        : "+l"(acc[p][j]) : "l"(a2[p]), "l"(b2));
            }
        }
        __syncthreads();
    }

#pragma unroll
    for (int i = 0; i < 8; i++) {
        int row = rowbase + ty * 8 + i;
        bool inb = row < NN;
        bool addb = inb && (g_rowptr[row + 1] - g_rowptr[row]) > 0;
        float bmul = addb ? 1.f : 0.f;
        float v[J];
        float s = 0.f;
#pragma unroll
        for (int j = 0; j < J; j++) {
            float2 pr = *(const float2*)&acc[i >> 1][j];
            float a = (i & 1) ? pr.y : pr.x;
            v[j] = a + bmul * bias[tx + 16 * j];
            s += v[j];
        }
#pragma unroll
        for (int o = 1; o < 16; o <<= 1) s += __shfl_xor_sync(0xffffffffu, s, o);
        float mu = s * (1.f / (float)OUT);
        float vs = 0.f;
#pragma unroll
        for (int j = 0; j < J; j++) { float d = v[j] - mu; vs += d * d; }
#pragma unroll
        for (int o = 1; o < 16; o <<= 1) vs += __shfl_xor_sync(0xffffffffu, vs, o);
        float rstd = rsqrtf(vs * (1.f / (float)OUT) + LN_EPS);
        if (inb) {
#pragma unroll
            for (int j = 0; j < J; j++) {
                int c = tx + 16 * j;
                float y = fmaxf((v[j] - mu) * rstd * gam[c] + bet[c], 0.f);
                outH[(size_t)row * OUT + c] = __float2half(y);
            }
        }
    }
}

// ---------------- HMMA GEMM via mma.sync m16n8k16 ----------------------------
// A [row][k] fp16 row-major, W [n][k] fp16 row-major (= col-major KxN B operand).
// Block: 256 threads / 8 warps, 128 rows (16 per warp), full K=128 in smem.
// Smem rows padded to 136 halves (17x16B) -> ldmatrix conflict-free, uint4-aligned.
template <int NOUT, bool LN, bool RELU, bool DEGMASK>
__global__ void __launch_bounds__(256)
k_gemm_mma(const __half* __restrict__ Ain, const __half* __restrict__ Wh,
           const float* __restrict__ bias, const float* __restrict__ gam,
           const float* __restrict__ bet, __half* __restrict__ outH) {
    constexpr int Q = NOUT / 8;           // n-tiles per warp-row-strip
    constexpr int LDS = 136;              // halves per smem row
    extern __shared__ __align__(16) char smem[];
    float*  ep = (float*)smem;                          // bias|gam|bet (NOUT each)
    __half* As = (__half*)(smem + 2048);                // 128 x LDS
    __half* Bs = As + 128 * LDS;                        // NOUT x LDS

    int tid = threadIdx.x;
    int w = tid >> 5, lane = tid & 31;
    int rowbase = blockIdx.x * 128;

    if (tid < NOUT) {
        ep[tid] = bias[tid];
        if (LN) { ep[NOUT + tid] = gam[tid]; ep[2 * NOUT + tid] = bet[tid]; }
    }
    // A tile
#pragma unroll
    for (int l = tid; l < 128 * 16; l += 256) {
        int r = l >> 4, c8 = l & 15;
        int row = rowbase + r;
        uint4 v = make_uint4(0u, 0u, 0u, 0u);
        if (row < NN) v = *(const uint4*)(Ain + (size_t)row * 128 + c8 * 8);
        *(uint4*)(As + r * LDS + c8 * 8) = v;
    }
    // B tile (weights)
#pragma unroll
    for (int l = tid; l < NOUT * 16; l += 256) {
        int r = l >> 4, c8 = l & 15;
        *(uint4*)(Bs + r * LDS + c8 * 8) = *(const uint4*)(Wh + (size_t)r * 128 + c8 * 8);
    }
    __syncthreads();

    // per-lane ldmatrix addresses
    uint32_t sA = smem_u32(As);
    uint32_t sB = smem_u32(Bs);
    int ar = w * 16 + (lane & 15);
    uint32_t a_addr0 = sA + (uint32_t)(ar * LDS + (lane >> 4) * 8) * 2;
    int rb = lane & 7;
    int cb = ((lane >> 3) & 1) * 8;
    uint32_t b_addr0 = sB + (uint32_t)(rb * LDS + cb) * 2;

    float acc[Q][4];
#pragma unroll
    for (int q = 0; q < Q; q++)
#pragma unroll
        for (int i = 0; i < 4; i++) acc[q][i] = 0.f;

#pragma unroll
    for (int kk = 0; kk < 8; kk++) {
        uint32_t a0, a1, a2, a3;
        asm volatile("ldmatrix.sync.aligned.m8n8.x4.shared.b16 {%0,%1,%2,%3}, [%4];"
                     : "=r"(a0), "=r"(a1), "=r"(a2), "=r"(a3)
                     : "r"(a_addr0 + kk * 32));
#pragma unroll
        for (int q = 0; q < Q; q++) {
            uint32_t b0, b1;
            asm volatile("ldmatrix.sync.aligned.m8n8.x2.shared.b16 {%0,%1}, [%2];"
                         : "=r"(b0), "=r"(b1)
                         : "r"(b_addr0 + (uint32_t)(q * 8 * LDS) * 2 + kk * 32));
            asm volatile(
                "mma.sync.aligned.m16n8k16.row.col.f32.f16.f16.f32 "
                "{%0,%1,%2,%3}, {%4,%5,%6,%7}, {%8,%9}, {%0,%1,%2,%3};"
                : "+f"(acc[q][0]), "+f"(acc[q][1]), "+f"(acc[q][2]), "+f"(acc[q][3])
                : "r"(a0), "r"(a1), "r"(a2), "r"(a3), "r"(b0), "r"(b1));
        }
    }

    // epilogue: rows (w*16 + lane/4) and (+8); cols q*8 + (lane%3)... (lane&3)*2
    int row0 = rowbase + w * 16 + (lane >> 2);
#pragma unroll
    for (int rr = 0; rr < 2; rr++) {
        int row = row0 + rr * 8;
        bool inb = row < NN;
        float bmul = 1.f;
        if (DEGMASK) bmul = (inb && (g_rowptr[row + 1] - g_rowptr[row]) > 0) ? 1.f : 0.f;
        float v[2 * Q];
        float s = 0.f;
#pragma unroll
        for (int q = 0; q < Q; q++) {
            int col = q * 8 + (lane & 3) * 2;
            float x0 = acc[q][rr * 2 + 0] + bmul * ep[col];
            float x1 = acc[q][rr * 2 + 1] + bmul * ep[col + 1];
            v[2 * q] = x0; v[2 * q + 1] = x1;
            s += x0 + x1;
        }
        if (LN) {
            s += __shfl_xor_sync(0xffffffffu, s, 1);
            s += __shfl_xor_sync(0xffffffffu, s, 2);
            float mu = s * (1.f / (float)NOUT);
            float vs = 0.f;
#pragma unroll
            for (int j = 0; j < 2 * Q; j++) { float d = v[j] - mu; vs += d * d; }
            vs += __shfl_xor_sync(0xffffffffu, vs, 1);
            vs += __shfl_xor_sync(0xffffffffu, vs, 2);
            float rstd = rsqrtf(vs * (1.f / (float)NOUT) + LN_EPS);
#pragma unroll
            for (int q = 0; q < Q; q++) {
                int col = q * 8 + (lane & 3) * 2;
                float y0 = (v[2 * q]     - mu) * rstd * ep[NOUT + col]     + ep[2 * NOUT + col];
                float y1 = (v[2 * q + 1] - mu) * rstd * ep[NOUT + col + 1] + ep[2 * NOUT + col + 1];
                if (RELU) { y0 = fmaxf(y0, 0.f); y1 = fmaxf(y1, 0.f); }
                v[2 * q] = y0; v[2 * q + 1] = y1;
            }
        }
        if (inb) {
#pragma unroll
            for (int q = 0; q < Q; q++) {
                int col = q * 8 + (lane & 3) * 2;
                *(__half2*)(outH + (size_t)row * NOUT + col) =
                    __floats2half2_rn(v[2 * q], v[2 * q + 1]);
            }
        }
    }
}

// ---------------- launch -----------------------------------------------------
extern "C" void kernel_launch(void* const* d_in, const int* in_sizes, int n_in,
                              void* d_out, int out_size) {
    const float* feat = (const float*)d_in[0];
    const int*   ei   = (const int*)d_in[1];
    const float* W0 = (const float*)d_in[2];
    const float* b0 = (const float*)d_in[3];
    const float* W1 = (const float*)d_in[4];
    const float* b1 = (const float*)d_in[5];
    const float* W2 = (const float*)d_in[6];
    const float* b2 = (const float*)d_in[7];
    const float* g0 = (const float*)d_in[8];
    const float* be0 = (const float*)d_in[9];
    const float* g1 = (const float*)d_in[10];
    const float* be1 = (const float*)d_in[11];
    const float* g2 = (const float*)d_in[12];
    const float* be2 = (const float*)d_in[13];
    float* out = (float*)d_out;

    const int* src = ei;
    const int* tgt = ei + NE;

    float* bufA = nullptr;
    __half *h0 = nullptr, *h1 = nullptr, *act1h = nullptr, *y1h = nullptr;
    __half *w1h = nullptr, *w2h = nullptr;
    cudaGetSymbolAddress((void**)&bufA, g_bufA);
    cudaGetSymbolAddress((void**)&h0, g_h0);
    cudaGetSymbolAddress((void**)&h1, g_h1);
    cudaGetSymbolAddress((void**)&act1h, g_act1h);
    cudaGetSymbolAddress((void**)&y1h, g_y1h);
    cudaGetSymbolAddress((void**)&w1h, g_w1h);
    cudaGetSymbolAddress((void**)&w2h, g_w2h);

    const int SMEM1 = 2048 + (128 + 128) * 136 * 2;   // 71680 (N=128)
    const int SMEM2 = 2048 + (128 + 64) * 136 * 2;    // 54272 (N=64)
    cudaFuncSetAttribute(k_gemm_mma<128, true, true, true>,
                         cudaFuncAttributeMaxDynamicSharedMemorySize, SMEM1);
    cudaFuncSetAttribute(k_gemm_mma<64, false, false, false>,
                         cudaFuncAttributeMaxDynamicSharedMemorySize, SMEM2);

    const int TPB = 256;
    // CSR build
    k_zero_deg<<<(NN + TPB - 1) / TPB, TPB>>>();
    k_count<<<(NE + TPB - 1) / TPB, TPB>>>(tgt);
    k_scan1<<<NB, 256>>>();
    k_scan2<<<1, 128>>>();
    k_scan3<<<NB, 256>>>();
    k_scatter<<<(NE + TPB - 1) / TPB, TPB>>>(src, tgt);

    // conversions
    k_feat2h<<<(NN * FPAD + TPB - 1) / TPB, TPB>>>(feat);
    k_w2h<<<(HDIM * HDIM + DOUT * HDIM + TPB - 1) / TPB, TPB>>>(W1, W2);

    int agg_blocks = (NN + 7) / 8;
    int gemm_blocks = (NN + 127) / 128;

    // Layer 0: agg(16 fp16) -> FFMA2 GEMM(16->128)+LN+ReLU -> fp16 h0
    k_agg_small<<<agg_blocks, TPB>>>(bufA);
    k_gemm0<16, FIN, HDIM><<<gemm_blocks, 256>>>(bufA, W0, b0, g0, be0, h0);

    // Layer 1: agg(128 fp16) -> HMMA GEMM(128->128)+LN+ReLU -> fp16 y1h
    k_agg128h<<<agg_blocks, TPB>>>();
    k_gemm_mma<128, true, true, true>
        <<<gemm_blocks, 256, SMEM1>>>(act1h, w1h, b1, g1, be1, y1h);

    // Layer 2: HMMA GEMM(128->64)+bias -> fp16 h1, then agg(64)+LN -> out
    k_gemm_mma<64, false, false, false>
        <<<gemm_blocks, 256, SMEM2>>>(y1h, w2h, b2, nullptr, nullptr, h1);
    k_agg64_ln<<<agg_blocks, TPB>>>(g2, be2, out);
}

// round 17
// speedup vs baseline: 2.6687x; 1.0755x over previous
#include <cuda_runtime.h>
#include <cuda_fp16.h>
#include <cstdint>

#define NN   100000
#define NE   1600000
#define FIN  11
#define FPAD 16
#define HDIM 128
#define DOUT 64
#define LN_EPS 1e-5f
#define NB   ((NN + 1023) / 1024)

// ---------------- scratch (static device globals; no allocation) -------------
__device__ int    g_deg[NN];
__device__ int    g_rowptr[NN + 1];
__device__ int    g_cursor[NN];
__device__ int    g_srcsorted[NE];
__device__ int    g_bsum[128];
__device__ float  g_bufA[(size_t)NN * FPAD];   // agg_small out (fp32)
__device__ __half g_h0[(size_t)NN * HDIM];     // gemm0 out (gathered by agg128)
__device__ __half g_act1h[(size_t)NN * HDIM];  // agg128 out = gemm12 A (fp16)
__device__ __half g_h1[(size_t)NN * DOUT];     // gemm12 out (gathered by agg64)
__device__ __half g_fh[(size_t)NN * FPAD];     // padded fp16 features
__device__ __half g_w1h[HDIM * HDIM];          // W1 fp16
__device__ __half g_w2h[DOUT * HDIM];          // W2 fp16

__device__ __forceinline__ uint32_t smem_u32(const void* p) {
    uint32_t a;
    asm("{ .reg .u64 t; cvta.to.shared.u64 t, %1; cvt.u32.u64 %0, t; }"
        : "=r"(a) : "l"(p));
    return a;
}

__device__ __forceinline__ float warpsum(float v) {
#pragma unroll
    for (int o = 16; o; o >>= 1) v += __shfl_xor_sync(0xffffffffu, v, o);
    return v;
}
__device__ __forceinline__ int warpsum_i(int v) {
#pragma unroll
    for (int o = 16; o; o >>= 1) v += __shfl_xor_sync(0xffffffffu, v, o);
    return v;
}

// ---------------- prep: zero deg + fp16 conversions --------------------------
__global__ void k_prep(const float* __restrict__ feat,
                       const float* __restrict__ W1,
                       const float* __restrict__ W2) {
    int i = blockIdx.x * blockDim.x + threadIdx.x;
    if (i < NN) g_deg[i] = 0;
    if (i < NN * FPAD) {
        int n = i >> 4, c = i & 15;
        g_fh[i] = (c < FIN) ? __float2half(feat[(size_t)n * FIN + c]) : __float2half(0.f);
    } else {
        int j = i - NN * FPAD;
        if (j < HDIM * HDIM) g_w1h[j] = __float2half(W1[j]);
        else {
            int k = j - HDIM * HDIM;
            if (k < DOUT * HDIM) g_w2h[k] = __float2half(W2[k]);
        }
    }
}

// ---------------- CSR build --------------------------------------------------
__global__ void k_count4(const int4* __restrict__ tgt4) {
    int e = blockIdx.x * blockDim.x + threadIdx.x;
    if (e < NE / 4) {
        int4 v = tgt4[e];
        atomicAdd(&g_deg[v.x], 1);
        atomicAdd(&g_deg[v.y], 1);
        atomicAdd(&g_deg[v.z], 1);
        atomicAdd(&g_deg[v.w], 1);
    }
}

__global__ void k_scan1() {
    __shared__ int ws[8];
    int b = blockIdx.x, t = threadIdx.x;
    int base = b * 1024 + t * 4;
    int s = 0;
#pragma unroll
    for (int i = 0; i < 4; i++) {
        int idx = base + i;
        if (idx < NN) s += g_deg[idx];
    }
    s = warpsum_i(s);
    if ((t & 31) == 0) ws[t >> 5] = s;
    __syncthreads();
    if (t < 8) {
        int v = ws[t];
#pragma unroll
        for (int o = 4; o; o >>= 1) v += __shfl_xor_sync(0xffu, v, o);
        if (t == 0) g_bsum[b] = v;
    }
}

// merged stage 2+3: block offset from g_bsum + local scan -> rowptr/cursor
__global__ void k_scanB() {
    __shared__ int ws[8];
    __shared__ int s_off;
    int b = blockIdx.x, t = threadIdx.x;
    if (t < 32) {
        int o = 0;
        for (int i = t; i < b; i += 32) o += g_bsum[i];
        o = warpsum_i(o);
        if (t == 0) s_off = o;
    }
    int base = b * 1024 + t * 4;
    int d[4];
    int s = 0;
#pragma unroll
    for (int i = 0; i < 4; i++) {
        int idx = base + i;
        d[i] = (idx < NN) ? g_deg[idx] : 0;
        s += d[i];
    }
    int lane = t & 31, w = t >> 5;
    int incl = s;
#pragma unroll
    for (int o = 1; o < 32; o <<= 1) {
        int u = __shfl_up_sync(0xffffffffu, incl, o);
        if (lane >= o) incl += u;
    }
    if (lane == 31) ws[w] = incl;
    __syncthreads();
    int woff = 0;
#pragma unroll
    for (int i = 0; i < 8; i++) woff += (i < w) ? ws[i] : 0;
    int run = s_off + woff + incl - s;
#pragma unroll
    for (int i = 0; i < 4; i++) {
        int idx = base + i;
        if (idx < NN) {
            g_rowptr[idx] = run;
            g_cursor[idx] = run;
            run += d[i];
        }
    }
    if (b == 0 && t == 0) g_rowptr[NN] = NE;
}

__global__ void k_scatter4(const int4* __restrict__ src4, const int4* __restrict__ tgt4) {
    int e = blockIdx.x * blockDim.x + threadIdx.x;
    if (e < NE / 4) {
        int4 tv = tgt4[e];
        int4 sv = src4[e];
        int p;
        p = atomicAdd(&g_cursor[tv.x], 1); g_srcsorted[p] = sv.x;
        p = atomicAdd(&g_cursor[tv.y], 1); g_srcsorted[p] = sv.y;
        p = atomicAdd(&g_cursor[tv.z], 1); g_srcsorted[p] = sv.z;
        p = atomicAdd(&g_cursor[tv.w], 1); g_srcsorted[p] = sv.w;
    }
}

// ---------------- aggregation kernels ----------------------------------------
__global__ void k_agg_small(float* __restrict__ out) {
    int n    = (blockIdx.x * blockDim.x + threadIdx.x) >> 5;
    int lane = threadIdx.x & 31;
    if (n >= NN) return;
    int beg = g_rowptr[n], end = g_rowptr[n + 1];
    float acc = 0.f;
    for (int base = beg; base < end; base += 32) {
        int idx = (base + lane < end) ? g_srcsorted[base + lane] : 0;
        int cnt = min(32, end - base);
        for (int j = 0; j < cnt; j += 2) {
            int s0 = __shfl_sync(0xffffffffu, idx, j);
            int s1 = __shfl_sync(0xffffffffu, idx, (j + 1) & 31);
            int s  = (lane < 16) ? s0 : ((j + 1 < cnt) ? s1 : -1);
            if (s >= 0) acc += __half2float(g_fh[(size_t)s * FPAD + (lane & 15)]);
        }
    }
    acc += __shfl_down_sync(0xffffffffu, acc, 16);
    float inv = 1.f / (float)max(end - beg, 1);
    if (lane < 16) out[(size_t)n * FPAD + lane] = acc * inv;
}

// mean-aggregate 128-dim fp16 rows -> fp16 out (gemm12 A operand)
__global__ void k_agg128h() {
    int n    = (blockIdx.x * blockDim.x + threadIdx.x) >> 5;
    int lane = threadIdx.x & 31;
    if (n >= NN) return;
    int beg = g_rowptr[n], end = g_rowptr[n + 1];
    float4 acc = make_float4(0.f, 0.f, 0.f, 0.f);
    for (int base = beg; base < end; base += 32) {
        int idx = (base + lane < end) ? g_srcsorted[base + lane] : 0;
        int cnt = min(32, end - base);
#pragma unroll 4
        for (int j = 0; j < cnt; j++) {
            int s = __shfl_sync(0xffffffffu, idx, j);
            uint2 raw = *(const uint2*)(g_h0 + (size_t)s * HDIM + lane * 4);
            float2 f0 = __half22float2(*(__half2*)&raw.x);
            float2 f1 = __half22float2(*(__half2*)&raw.y);
            acc.x += f0.x; acc.y += f0.y; acc.z += f1.x; acc.w += f1.y;
        }
    }
    float inv = 1.f / (float)max(end - beg, 1);
    __half2 o0 = __floats2half2_rn(acc.x * inv, acc.y * inv);
    __half2 o1 = __floats2half2_rn(acc.z * inv, acc.w * inv);
    uint2 o;
    o.x = *(uint32_t*)&o0; o.y = *(uint32_t*)&o1;
    *(uint2*)(g_act1h + (size_t)n * HDIM + lane * 4) = o;
}

__global__ void k_agg64_ln(const float* __restrict__ gam,
                           const float* __restrict__ bet,
                           float* __restrict__ out) {
    int n    = (blockIdx.x * blockDim.x + threadIdx.x) >> 5;
    int lane = threadIdx.x & 31;
    if (n >= NN) return;
    int beg = g_rowptr[n], end = g_rowptr[n + 1];
    float2 acc = make_float2(0.f, 0.f);
    for (int base = beg; base < end; base += 32) {
        int idx = (base + lane < end) ? g_srcsorted[base + lane] : 0;
        int cnt = min(32, end - base);
#pragma unroll 4
        for (int j = 0; j < cnt; j++) {
            int s = __shfl_sync(0xffffffffu, idx, j);
            float2 f = __half22float2(*(const __half2*)(g_h1 + (size_t)s * DOUT + lane * 2));
            acc.x += f.x; acc.y += f.y;
        }
    }
    float inv = 1.f / (float)max(end - beg, 1);
    acc.x *= inv; acc.y *= inv;
    float mu = warpsum(acc.x + acc.y) * (1.f / (float)DOUT);
    float dx = acc.x - mu, dy = acc.y - mu;
    float var = warpsum(dx * dx + dy * dy) * (1.f / (float)DOUT);
    float rstd = rsqrtf(var + LN_EPS);
    int c = lane * 2;
    float2 r;
    r.x = dx * rstd * gam[c]     + bet[c];
    r.y = dy * rstd * gam[c + 1] + bet[c + 1];
    *(float2*)(out + (size_t)n * DOUT + c) = r;
}

// ---------------- layer-0 GEMM (FFMA2, K=16) ---------------------------------
template <int K, int KW, int OUT>
__global__ void __launch_bounds__(256)
k_gemm0(const float* __restrict__ A, const float* __restrict__ W,
        const float* __restrict__ bias, const float* __restrict__ gam,
        const float* __restrict__ bet, __half* __restrict__ outH) {
    constexpr int TM = 128;
    constexpr int J  = OUT / 16;
    __shared__ __align__(16) float  As[16][TM + 4];
    __shared__ __align__(16) float2 Bs2[16][OUT];

    int tid = threadIdx.x;
    int tx = tid & 15, ty = tid >> 4;
    int rowbase = blockIdx.x * TM;

    unsigned long long acc[4][J];
#pragma unroll
    for (int p = 0; p < 4; p++)
#pragma unroll
        for (int j = 0; j < J; j++) acc[p][j] = 0ull;

    for (int k0 = 0; k0 < K; k0 += 16) {
#pragma unroll
        for (int l = tid; l < TM * 4; l += 256) {
            int m = l >> 2, q = l & 3;
            int row = rowbase + m;
            float4 v = make_float4(0.f, 0.f, 0.f, 0.f);
            if (row < NN) v = *(const float4*)(A + (size_t)row * K + k0 + q * 4);
            As[q * 4 + 0][m] = v.x;
            As[q * 4 + 1][m] = v.y;
            As[q * 4 + 2][m] = v.z;
            As[q * 4 + 3][m] = v.w;
        }
#pragma unroll
        for (int l = tid; l < 16 * OUT; l += 256) {
            int c = l >> 4, k = l & 15;
            int kk = k0 + k;
            float w = (kk < KW) ? W[(size_t)c * KW + kk] : 0.f;
            Bs2[k][c] = make_float2(w, w);
        }
        __syncthreads();
#pragma unroll
        for (int k = 0; k < 16; k++) {
            unsigned long long a2[4];
#pragma unroll
            for (int p = 0; p < 4; p++)
                a2[p] = *(const unsigned long long*)&As[k][ty * 8 + 2 * p];
#pragma unroll
            for (int j = 0; j < J; j++) {
                unsigned long long b2 = *(const unsigned long long*)&Bs2[k][tx + 16 * j];
#pragma unroll
                for (int p = 0; p < 4; p++)
                    asm("fma.rn.f32x2 %0, %1, %2, %0;"
                        : "+l"(acc[p][j]) : "l"(a2[p]), "l"(b2));
            }
        }
        __syncthreads();
    }

#pragma unroll
    for (int i = 0; i < 8; i++) {
        int row = rowbase + ty * 8 + i;
        bool inb = row < NN;
        bool addb = inb && (g_rowptr[row + 1] - g_rowptr[row]) > 0;
        float bmul = addb ? 1.f : 0.f;
        float v[J];
        float s = 0.f;
#pragma unroll
        for (int j = 0; j < J; j++) {
            float2 pr = *(const float2*)&acc[i >> 1][j];
            float a = (i & 1) ? pr.y : pr.x;
            v[j] = a + bmul * bias[tx + 16 * j];
            s += v[j];
        }
#pragma unroll
        for (int o = 1; o < 16; o <<= 1) s += __shfl_xor_sync(0xffffffffu, s, o);
        float mu = s * (1.f / (float)OUT);
        float vs = 0.f;
#pragma unroll
        for (int j = 0; j < J; j++) { float d = v[j] - mu; vs += d * d; }
#pragma unroll
        for (int o = 1; o < 16; o <<= 1) vs += __shfl_xor_sync(0xffffffffu, vs, o);
        float rstd = rsqrtf(vs * (1.f / (float)OUT) + LN_EPS);
        if (inb) {
#pragma unroll
            for (int j = 0; j < J; j++) {
                int c = tx + 16 * j;
                float y = fmaxf((v[j] - mu) * rstd * gam[c] + bet[c], 0.f);
                outH[(size_t)row * OUT + c] = __float2half(y);
            }
        }
    }
}

// ---------------- fused HMMA GEMM1(+LN+ReLU)+GEMM2(+bias) --------------------
// A = act1h [row][128] fp16; W1 [128][128]; W2 [64][128] fp16 row-major.
// Each warp owns a 16-row strip: MMA1 -> LN/ReLU epilogue writes y1 fp16 back
// into its OWN strip of the A smem tile (warp-private, __syncwarp only), then
// MMA2 against W2 tile -> +b2 -> h1.
__global__ void __launch_bounds__(256)
k_gemm12(const __half* __restrict__ Ain,
         const float* __restrict__ b1, const float* __restrict__ g1,
         const float* __restrict__ be1, const float* __restrict__ b2,
         __half* __restrict__ outH) {
    constexpr int LDS = 136;
    extern __shared__ __align__(16) char smem[];
    float*  ep  = (float*)smem;                 // b1[128] g1[128] be1[128] b2[64]
    __half* As  = (__half*)(smem + 2048);       // 128 x LDS
    __half* Bs1 = As + 128 * LDS;               // 128 x LDS
    __half* Bs2 = Bs1 + 128 * LDS;              // 64 x LDS

    int tid = threadIdx.x;
    int w = tid >> 5, lane = tid & 31;
    int rowbase = blockIdx.x * 128;

    if (tid < 128) {
        ep[tid] = b1[tid];
        ep[128 + tid] = g1[tid];
        ep[256 + tid] = be1[tid];
        if (tid < 64) ep[384 + tid] = b2[tid];
    }
#pragma unroll
    for (int l = tid; l < 128 * 16; l += 256) {
        int r = l >> 4, c8 = l & 15;
        int row = rowbase + r;
        uint4 v = make_uint4(0u, 0u, 0u, 0u);
        if (row < NN) v = *(const uint4*)(Ain + (size_t)row * 128 + c8 * 8);
        *(uint4*)(As + r * LDS + c8 * 8) = v;
    }
#pragma unroll
    for (int l = tid; l < 128 * 16; l += 256) {
        int r = l >> 4, c8 = l & 15;
        *(uint4*)(Bs1 + r * LDS + c8 * 8) = *(const uint4*)(g_w1h + (size_t)r * 128 + c8 * 8);
    }
#pragma unroll
    for (int l = tid; l < 64 * 16; l += 256) {
        int r = l >> 4, c8 = l & 15;
        *(uint4*)(Bs2 + r * LDS + c8 * 8) = *(const uint4*)(g_w2h + (size_t)r * 128 + c8 * 8);
    }
    __syncthreads();

    uint32_t sA  = smem_u32(As);
    uint32_t sB1 = smem_u32(Bs1);
    uint32_t sB2 = smem_u32(Bs2);
    int ar = w * 16 + (lane & 15);
    uint32_t a_addr0 = sA + (uint32_t)(ar * LDS + (lane >> 4) * 8) * 2;
    int rb = lane & 7;
    int cb = ((lane >> 3) & 1) * 8;
    uint32_t b1_addr0 = sB1 + (uint32_t)(rb * LDS + cb) * 2;
    uint32_t b2_addr0 = sB2 + (uint32_t)(rb * LDS + cb) * 2;

    // ---- MMA1: 128x128x128 ----
    float acc[16][4];
#pragma unroll
    for (int q = 0; q < 16; q++)
#pragma unroll
        for (int i = 0; i < 4; i++) acc[q][i] = 0.f;

#pragma unroll
    for (int kk = 0; kk < 8; kk++) {
        uint32_t a0, a1, a2, a3;
        asm volatile("ldmatrix.sync.aligned.m8n8.x4.shared.b16 {%0,%1,%2,%3}, [%4];"
                     : "=r"(a0), "=r"(a1), "=r"(a2), "=r"(a3)
                     : "r"(a_addr0 + kk * 32));
#pragma unroll
        for (int q = 0; q < 16; q++) {
            uint32_t b0v, b1v;
            asm volatile("ldmatrix.sync.aligned.m8n8.x2.shared.b16 {%0,%1}, [%2];"
                         : "=r"(b0v), "=r"(b1v)
                         : "r"(b1_addr0 + (uint32_t)(q * 8 * LDS) * 2 + kk * 32));
            asm volatile(
                "mma.sync.aligned.m16n8k16.row.col.f32.f16.f16.f32 "
                "{%0,%1,%2,%3}, {%4,%5,%6,%7}, {%8,%9}, {%0,%1,%2,%3};"
                : "+f"(acc[q][0]), "+f"(acc[q][1]), "+f"(acc[q][2]), "+f"(acc[q][3])
                : "r"(a0), "r"(a1), "r"(a2), "r"(a3), "r"(b0v), "r"(b1v));
        }
    }

    // ---- epilogue1: +b1(deg-masked), LN, ReLU -> fp16 into own As strip ----
    int rl0 = w * 16 + (lane >> 2);
#pragma unroll
    for (int rr = 0; rr < 2; rr++) {
        int rloc = rl0 + rr * 8;
        int row = rowbase + rloc;
        bool inb = row < NN;
        float bmul = (inb && (g_rowptr[row + 1] - g_rowptr[row]) > 0) ? 1.f : 0.f;
        float v[32];
        float s = 0.f;
#pragma unroll
        for (int q = 0; q < 16; q++) {
            int col = q * 8 + (lane & 3) * 2;
            float x0 = acc[q][rr * 2 + 0] + bmul * ep[col];
            float x1 = acc[q][rr * 2 + 1] + bmul * ep[col + 1];
            v[2 * q] = x0; v[2 * q + 1] = x1;
            s += x0 + x1;
        }
        s += __shfl_xor_sync(0xffffffffu, s, 1);
        s += __shfl_xor_sync(0xffffffffu, s, 2);
        float mu = s * (1.f / 128.f);
        float vs = 0.f;
#pragma unroll
        for (int j = 0; j < 32; j++) { float d = v[j] - mu; vs += d * d; }
        vs += __shfl_xor_sync(0xffffffffu, vs, 1);
        vs += __shfl_xor_sync(0xffffffffu, vs, 2);
        float rstd = rsqrtf(vs * (1.f / 128.f) + LN_EPS);
#pragma unroll
        for (int q = 0; q < 16; q++) {
            int col = q * 8 + (lane & 3) * 2;
            float y0 = fmaxf((v[2 * q]     - mu) * rstd * ep[128 + col]     + ep[256 + col], 0.f);
            float y1 = fmaxf((v[2 * q + 1] - mu) * rstd * ep[128 + col + 1] + ep[256 + col + 1], 0.f);
            *(__half2*)(As + rloc * LDS + col) = __floats2half2_rn(y0, y1);
        }
    }
    __syncwarp();

    // ---- MMA2: 128x64x128 on y1 (in As) x W2 ----
    float acc2[8][4];
#pragma unroll
    for (int q = 0; q < 8; q++)
#pragma unroll
        for (int i = 0; i < 4; i++) acc2[q][i] = 0.f;

#pragma unroll
    for (int kk = 0; kk < 8; kk++) {
        uint32_t a0, a1, a2, a3;
        asm volatile("ldmatrix.sync.aligned.m8n8.x4.shared.b16 {%0,%1,%2,%3}, [%4];"
                     : "=r"(a0), "=r"(a1), "=r"(a2), "=r"(a3)
                     : "r"(a_addr0 + kk * 32));
#pragma unroll
        for (int q = 0; q < 8; q++) {
            uint32_t b0v, b1v;
            asm volatile("ldmatrix.sync.aligned.m8n8.x2.shared.b16 {%0,%1}, [%2];"
                         : "=r"(b0v), "=r"(b1v)
                         : "r"(b2_addr0 + (uint32_t)(q * 8 * LDS) * 2 + kk * 32));
            asm volatile(
                "mma.sync.aligned.m16n8k16.row.col.f32.f16.f16.f32 "
                "{%0,%1,%2,%3}, {%4,%5,%6,%7}, {%8,%9}, {%0,%1,%2,%3};"
                : "+f"(acc2[q][0]), "+f"(acc2[q][1]), "+f"(acc2[q][2]), "+f"(acc2[q][3])
                : "r"(a0), "r"(a1), "r"(a2), "r"(a3), "r"(b0v), "r"(b1v));
        }
    }

    // ---- epilogue2: +b2 (unmasked) -> h1 fp16 ----
#pragma unroll
    for (int rr = 0; rr < 2; rr++) {
        int row = rowbase + rl0 + rr * 8;
        if (row >= NN) continue;
#pragma unroll
        for (int q = 0; q < 8; q++) {
            int col = q * 8 + (lane & 3) * 2;
            float x0 = acc2[q][rr * 2 + 0] + ep[384 + col];
            float x1 = acc2[q][rr * 2 + 1] + ep[384 + col + 1];
            *(__half2*)(outH + (size_t)row * DOUT + col) = __floats2half2_rn(x0, x1);
        }
    }
}

// ---------------- launch -----------------------------------------------------
extern "C" void kernel_launch(void* const* d_in, const int* in_sizes, int n_in,
                              void* d_out, int out_size) {
    const float* feat = (const float*)d_in[0];
    const int*   ei   = (const int*)d_in[1];
    const float* W0 = (const float*)d_in[2];
    const float* b0 = (const float*)d_in[3];
    const float* W1 = (const float*)d_in[4];
    const float* b1 = (const float*)d_in[5];
    const float* W2 = (const float*)d_in[6];
    const float* b2 = (const float*)d_in[7];
    const float* g0 = (const float*)d_in[8];
    const float* be0 = (const float*)d_in[9];
    const float* g1 = (const float*)d_in[10];
    const float* be1 = (const float*)d_in[11];
    const float* g2 = (const float*)d_in[12];
    const float* be2 = (const float*)d_in[13];
    float* out = (float*)d_out;

    const int* src = ei;
    const int* tgt = ei + NE;

    float* bufA = nullptr;
    __half *h0 = nullptr, *h1 = nullptr, *act1h = nullptr;
    cudaGetSymbolAddress((void**)&bufA, g_bufA);
    cudaGetSymbolAddress((void**)&h0, g_h0);
    cudaGetSymbolAddress((void**)&h1, g_h1);
    cudaGetSymbolAddress((void**)&act1h, g_act1h);

    const int SMEM12 = 2048 + (128 + 128 + 64) * 136 * 2;   // 89088
    cudaFuncSetAttribute(k_gemm12, cudaFuncAttributeMaxDynamicSharedMemorySize, SMEM12);

    const int TPB = 256;
    int prep_n = NN * FPAD + HDIM * HDIM + DOUT * HDIM;

    // prep (zero deg + conversions) runs before/independent of CSR chain
    k_prep<<<(prep_n + TPB - 1) / TPB, TPB>>>(feat, W1, W2);
    // CSR build
    k_count4<<<(NE / 4 + TPB - 1) / TPB, TPB>>>((const int4*)tgt);
    k_scan1<<<NB, 256>>>();
    k_scanB<<<NB, 256>>>();
    k_scatter4<<<(NE / 4 + TPB - 1) / TPB, TPB>>>((const int4*)src, (const int4*)tgt);

    int agg_blocks = (NN + 7) / 8;
    int gemm_blocks = (NN + 127) / 128;

    // Layer 0: agg(16 fp16) -> FFMA2 GEMM(16->128)+LN+ReLU -> fp16 h0
    k_agg_small<<<agg_blocks, TPB>>>(bufA);
    k_gemm0<16, FIN, HDIM><<<gemm_blocks, 256>>>(bufA, W0, b0, g0, be0, h0);

    // Layer 1+2 fused: agg(128 fp16) -> HMMA(128->128)+LN+ReLU -> HMMA(128->64)+b2 -> h1
    k_agg128h<<<agg_blocks, TPB>>>();
    k_gemm12<<<gemm_blocks, 256, SMEM12>>>(act1h, b1, g1, be1, b2, h1);

    // final: agg(64)+LN -> out
    k_agg64_ln<<<agg_blocks, TPB>>>(g2, be2, out);
}